// round 11
// baseline (speedup 1.0000x reference)
#include <cuda_runtime.h>

#define NN 1024
#define DD 128

// ---------------------------------------------------------------------------
// Device scratch (allocation-free)
// ---------------------------------------------------------------------------
__device__ float g_W1T [256 * DD];  // W1 transposed: [concat col c][k]
__device__ float g_PIB [NN * DD];   // pi + b1, row-major (for ci)
__device__ float g_PIBT[DD * NN];   // pi + b1, transposed [d][i]
__device__ float g_PJ  [NN * DD];   // pj, row-major (for cj)
__device__ float g_PJT [DD * NN];   // pj, transposed [d][j]
__device__ float g_W2H [DD];        // 0.5 * W2
__device__ float g_ci  [NN];
__device__ float g_cj  [NN];

// ---------------------------------------------------------------------------
// f32x2 packed helpers (sm_103a)
// ---------------------------------------------------------------------------
__device__ __forceinline__ unsigned long long pack2(float lo, float hi) {
    unsigned long long r;
    asm("mov.b64 %0, {%1, %2};" : "=l"(r) : "f"(lo), "f"(hi));
    return r;
}
__device__ __forceinline__ void unpack2(unsigned long long v, float& lo, float& hi) {
    asm("mov.b64 {%0, %1}, %2;" : "=f"(lo), "=f"(hi) : "l"(v));
}
__device__ __forceinline__ unsigned long long add2(unsigned long long a, unsigned long long b) {
    unsigned long long r;
    asm("add.rn.f32x2 %0, %1, %2;" : "=l"(r) : "l"(a), "l"(b));
    return r;
}
__device__ __forceinline__ unsigned long long fma2(unsigned long long a, unsigned long long b,
                                                   unsigned long long c) {
    unsigned long long r;
    asm("fma.rn.f32x2 %0, %1, %2, %3;" : "=l"(r) : "l"(a), "l"(b), "l"(c));
    return r;
}
#define ABS2_MASK 0x7FFFFFFF7FFFFFFFULL

// ---------------------------------------------------------------------------
// Kernel 0: W1T[c][k] = W1[k + (c>=128?128:0)][c&127]
// 32x32 smem tiles; reads and writes both coalesced; conflict-free (stride 33).
// Grid (8 c-tiles, 4 k-tiles) x (32,8) threads.
// ---------------------------------------------------------------------------
__global__ void __launch_bounds__(256) w1t_kernel(const float* __restrict__ W1)
{
    __shared__ float t[32][33];
    const int c0 = blockIdx.x * 32;
    const int k0 = blockIdx.y * 32;
    const int tx = threadIdx.x;          // 0..31
    const int ty = threadIdx.y;          // 0..7
    const int roff  = (c0 >= DD) ? DD : 0;
    const int dbase = c0 - roff;

    #pragma unroll
    for (int r = 0; r < 4; r++) {
        const int k = k0 + ty + r * 8;
        t[ty + r * 8][tx] = W1[(k + roff) * DD + dbase + tx];
    }
    __syncthreads();
    #pragma unroll
    for (int r = 0; r < 4; r++) {
        const int c = c0 + ty + r * 8;
        g_W1T[c * DD + k0 + tx] = t[tx][ty + r * 8];
    }
}

// ---------------------------------------------------------------------------
// Kernel A (v5): fused GEMM with k-vectorized W1T loads.
// 128 blocks x 512 threads. Thread = (concat col dc = tid&255, rowhalf h),
// 4 rows each. k-loop: 32 x LDG.128 from W1T row + 4 x LDS.128 (broadcast).
// ---------------------------------------------------------------------------
__global__ void __launch_bounds__(512, 1) prep_kernel(
    const float* __restrict__ z, const float* __restrict__ b1,
    const float* __restrict__ W2)
{
    __shared__ float zs[8][DD];
    const int tid = threadIdx.x;         // 0..511
    const int dc  = tid & 255;           // concat output column
    const int h   = tid >> 8;            // row half (0/1) -> rows 4h..4h+3
    const int i0  = blockIdx.x * 8;

    if (blockIdx.x == 0 && tid < DD) g_W2H[tid] = 0.5f * W2[tid];

    if (tid < 256)
        ((float4*)zs)[tid] = ((const float4*)(z + i0 * DD))[tid];
    __syncthreads();

    const float4* wrow = (const float4*)(g_W1T + dc * DD);
    const int r0 = 4 * h;

    float acc[4] = {0.f, 0.f, 0.f, 0.f};

    #pragma unroll 8
    for (int k4 = 0; k4 < 32; k4++) {
        const float4 w = __ldg(&wrow[k4]);
        #pragma unroll
        for (int ii = 0; ii < 4; ii++) {
            const float4 zv = *(const float4*)&zs[r0 + ii][k4 * 4];
            acc[ii] = fmaf(zv.x, w.x,
                      fmaf(zv.y, w.y,
                      fmaf(zv.z, w.z,
                      fmaf(zv.w, w.w, acc[ii]))));
        }
    }

    const bool is_pi = (dc < DD);
    const int  d     = is_pi ? dc : dc - DD;

    if (is_pi) {
        const float bb = __ldg(&b1[d]);
        #pragma unroll
        for (int ii = 0; ii < 4; ii++) acc[ii] += bb;
        #pragma unroll
        for (int ii = 0; ii < 4; ii++)
            g_PIB[(i0 + r0 + ii) * DD + d] = acc[ii];     // coalesced across dc
        *(float4*)&g_PIBT[d * NN + i0 + r0] = *(float4*)&acc[0];
    } else {
        #pragma unroll
        for (int ii = 0; ii < 4; ii++)
            g_PJ[(i0 + r0 + ii) * DD + d] = acc[ii];
        *(float4*)&g_PJT[d * NN + i0 + r0] = *(float4*)&acc[0];
    }
}

// ---------------------------------------------------------------------------
// Kernel B: ci[i] = g_PIB[i,:] . g_W2H ; cj[j] = g_PJ[j,:] . g_W2H
// ---------------------------------------------------------------------------
__global__ void __launch_bounds__(256) cicj_kernel()
{
    const int warp = blockIdx.x * 8 + (threadIdx.x >> 5);
    const int lane = threadIdx.x & 31;
    const bool is_ci = warp < NN;
    const int  row   = is_ci ? warp : warp - NN;
    const float* src = is_ci ? (g_PIB + row * DD) : (g_PJ + row * DD);

    float4 v = *(const float4*)(src + lane * 4);
    float4 w = *(const float4*)(g_W2H + lane * 4);
    float s = v.x * w.x + v.y * w.y + v.z * w.z + v.w * w.w;
    #pragma unroll
    for (int off = 16; off; off >>= 1)
        s += __shfl_down_sync(0xFFFFFFFFu, s, off);
    if (lane == 0) {
        if (is_ci) g_ci[row] = s; else g_cj[row] = s;
    }
}

// ---------------------------------------------------------------------------
// Kernel C (v4, unchanged): single pass.
// q[i,j] = ci[i] + cj[j] + sum_d w'_d |pi[d,i] + pj[d,j]| + b2
// Tile 64i x 32j, 256 threads: ty -> 4 i (2 f32x2 packs), tx -> 2 j.
// pj staged in smem pre-broadcast-packed {v,v}.
// ---------------------------------------------------------------------------
__global__ void __launch_bounds__(256, 3) pair_kernel(
    const float* __restrict__ b2, float* __restrict__ out)
{
    extern __shared__ char sm_raw[];
    float*              pisT = (float*)sm_raw;                        // 32 KB
    unsigned long long* pjp  = (unsigned long long*)(sm_raw + 32768); // 32 KB
    unsigned long long* w2p  = (unsigned long long*)(sm_raw + 65536); //  1 KB

    const int tx  = threadIdx.x;                // 0..15 -> 2 j
    const int ty  = threadIdx.y;                // 0..15 -> 4 i
    const int tid = ty * 16 + tx;
    const int ib  = blockIdx.y * 64;
    const int jb  = blockIdx.x * 32;

    #pragma unroll
    for (int it = 0; it < 8; it++) {
        const int idx = tid + it * 256;
        const int d = idx >> 4;
        const int q = idx & 15;
        *(float4*)&pisT[d * 64 + q * 4] =
            *(const float4*)&g_PIBT[d * NN + ib + q * 4];
    }
    #pragma unroll
    for (int it = 0; it < 16; it++) {
        const int idx = tid + it * 256;
        const int d  = idx >> 5;
        const int js = idx & 31;
        const float v = g_PJT[d * NN + jb + js];
        pjp[d * 32 + js] = pack2(v, v);
    }
    if (tid < DD) {
        const float w = g_W2H[tid];
        w2p[tid] = pack2(w, w);
    }
    __syncthreads();

    const int i0 = ty * 4;
    const int j0 = tx * 2;

    unsigned long long acc[2][2];
    acc[0][0] = acc[0][1] = acc[1][0] = acc[1][1] = 0ULL;

    #pragma unroll 8
    for (int d = 0; d < DD; d++) {
        const ulonglong2 aA = *(const ulonglong2*)&pisT[d * 64 + i0];
        const ulonglong2 bB = *(const ulonglong2*)&pjp [d * 32 + j0];
        const unsigned long long wd = w2p[d];

        unsigned long long t;
        t = add2(aA.x, bB.x) & ABS2_MASK;  acc[0][0] = fma2(wd, t, acc[0][0]);
        t = add2(aA.x, bB.y) & ABS2_MASK;  acc[0][1] = fma2(wd, t, acc[0][1]);
        t = add2(aA.y, bB.x) & ABS2_MASK;  acc[1][0] = fma2(wd, t, acc[1][0]);
        t = add2(aA.y, bB.y) & ABS2_MASK;  acc[1][1] = fma2(wd, t, acc[1][1]);
    }

    const int ig = ib + i0;
    const int jg = jb + j0;
    const float4 civ = *(const float4*)&g_ci[ig];
    const float2 cjv = *(const float2*)&g_cj[jg];
    const float  bb  = __ldg(b2);
    const float  cia[4] = { civ.x, civ.y, civ.z, civ.w };

    float v[4][2];
    #pragma unroll
    for (int p = 0; p < 2; p++)
        #pragma unroll
        for (int j = 0; j < 2; j++) {
            float lo, hi;
            unpack2(acc[p][j], lo, hi);
            v[2 * p][j]     = lo;
            v[2 * p + 1][j] = hi;
        }

    #pragma unroll
    for (int r = 0; r < 4; r++) {
        const float base = cia[r] + bb;
        float2 o;
        o.x = v[r][0] + cjv.x + base;
        o.y = v[r][1] + cjv.y + base;
        *(float2*)&out[(ig + r) * NN + jg] = o;
    }
}

// ---------------------------------------------------------------------------
// metadata order: z [1024*128], W1 [256*128], b1 [128], W2 [128], b2 [1]
// output: float32 [1024*1024]
// ---------------------------------------------------------------------------
extern "C" void kernel_launch(void* const* d_in, const int* in_sizes, int n_in,
                              void* d_out, int out_size)
{
    const float* z  = (const float*)d_in[0];
    const float* W1 = (const float*)d_in[1];
    const float* b1 = (const float*)d_in[2];
    const float* W2 = (const float*)d_in[3];
    const float* b2 = (const float*)d_in[4];
    float* out = (float*)d_out;

    const int smem_bytes = 65536 + 1024;
    cudaFuncSetAttribute(pair_kernel,
                         cudaFuncAttributeMaxDynamicSharedMemorySize, smem_bytes);

    dim3 tgrd(8, 4);
    dim3 tblk(32, 8);
    w1t_kernel<<<tgrd, tblk>>>(W1);

    prep_kernel<<<NN / 8, 512>>>(z, b1, W2);
    cicj_kernel<<<256, 256>>>();

    dim3 blk(16, 16);
    dim3 grd(NN / 32, NN / 64);
    pair_kernel<<<grd, blk, smem_bytes>>>(b2, out);
}

// round 12
// speedup vs baseline: 1.2613x; 1.2613x over previous
#include <cuda_runtime.h>

#define NN 1024
#define DD 128

// ---------------------------------------------------------------------------
// Device scratch (allocation-free)
// ---------------------------------------------------------------------------
__device__ float g_PIB [NN * DD];   // pi + b1, row-major (for ci)
__device__ float g_PIBT[DD * NN];   // pi + b1, transposed [d][i]
__device__ float g_PJ  [NN * DD];   // pj, row-major (for cj)
__device__ float g_PJT [DD * NN];   // pj, transposed [d][j]
__device__ float g_W2H [DD];        // 0.5 * W2
__device__ float g_ci  [NN];
__device__ float g_cj  [NN];

// ---------------------------------------------------------------------------
// f32x2 packed helpers (sm_103a)
// ---------------------------------------------------------------------------
__device__ __forceinline__ unsigned long long pack2(float lo, float hi) {
    unsigned long long r;
    asm("mov.b64 %0, {%1, %2};" : "=l"(r) : "f"(lo), "f"(hi));
    return r;
}
__device__ __forceinline__ void unpack2(unsigned long long v, float& lo, float& hi) {
    asm("mov.b64 {%0, %1}, %2;" : "=f"(lo), "=f"(hi) : "l"(v));
}
__device__ __forceinline__ unsigned long long add2(unsigned long long a, unsigned long long b) {
    unsigned long long r;
    asm("add.rn.f32x2 %0, %1, %2;" : "=l"(r) : "l"(a), "l"(b));
    return r;
}
__device__ __forceinline__ unsigned long long fma2(unsigned long long a, unsigned long long b,
                                                   unsigned long long c) {
    unsigned long long r;
    asm("fma.rn.f32x2 %0, %1, %2, %3;" : "=l"(r) : "l"(a), "l"(b), "l"(c));
    return r;
}
#define ABS2_MASK 0x7FFFFFFF7FFFFFFFULL

// ---------------------------------------------------------------------------
// Kernel A (v6): proven scalar-column GEMM, but 1024 threads/block.
// 128 blocks x 1024 threads: dc = tid&255 (concat column), h = tid>>8 -> 2
// rows each. Same coalesced W1 column loads + 16 MB L2 traffic as before,
// but 32 warps/SM where resident (was 8) -> issue-bound, not latency-bound.
// ---------------------------------------------------------------------------
__global__ void __launch_bounds__(1024, 1) prep_kernel(
    const float* __restrict__ z, const float* __restrict__ W1,
    const float* __restrict__ b1, const float* __restrict__ W2)
{
    __shared__ float zs[8][DD];
    const int tid = threadIdx.x;         // 0..1023
    const int dc  = tid & 255;           // concat output column
    const int h   = tid >> 8;            // 0..3 -> rows 2h, 2h+1
    const int i0  = blockIdx.x * 8;

    if (blockIdx.x == 0 && tid < DD) g_W2H[tid] = 0.5f * W2[tid];

    if (tid < 256)
        ((float4*)zs)[tid] = ((const float4*)(z + i0 * DD))[tid];
    __syncthreads();

    const bool is_pi = (dc < DD);
    const int  d     = is_pi ? dc : dc - DD;
    const float* wcol = is_pi ? (W1 + d) : (W1 + DD * DD + d);
    const int r0 = 2 * h;

    float a0 = 0.f, a1 = 0.f;

    #pragma unroll 16
    for (int k = 0; k < DD; k++) {
        const float w = __ldg(&wcol[k * DD]);   // coalesced across dc
        a0 = fmaf(zs[r0][k],     w, a0);
        a1 = fmaf(zs[r0 + 1][k], w, a1);
    }

    if (is_pi) {
        const float bb = __ldg(&b1[d]);
        a0 += bb; a1 += bb;
        g_PIB[(i0 + r0) * DD + d]     = a0;     // coalesced across dc
        g_PIB[(i0 + r0 + 1) * DD + d] = a1;
        *(float2*)&g_PIBT[d * NN + i0 + r0] = make_float2(a0, a1);
    } else {
        g_PJ[(i0 + r0) * DD + d]     = a0;
        g_PJ[(i0 + r0 + 1) * DD + d] = a1;
        *(float2*)&g_PJT[d * NN + i0 + r0] = make_float2(a0, a1);
    }
}

// ---------------------------------------------------------------------------
// Kernel B: ci[i] = g_PIB[i,:] . g_W2H ; cj[j] = g_PJ[j,:] . g_W2H
// ---------------------------------------------------------------------------
__global__ void __launch_bounds__(256) cicj_kernel()
{
    const int warp = blockIdx.x * 8 + (threadIdx.x >> 5);
    const int lane = threadIdx.x & 31;
    const bool is_ci = warp < NN;
    const int  row   = is_ci ? warp : warp - NN;
    const float* src = is_ci ? (g_PIB + row * DD) : (g_PJ + row * DD);

    float4 v = *(const float4*)(src + lane * 4);
    float4 w = *(const float4*)(g_W2H + lane * 4);
    float s = v.x * w.x + v.y * w.y + v.z * w.z + v.w * w.w;
    #pragma unroll
    for (int off = 16; off; off >>= 1)
        s += __shfl_down_sync(0xFFFFFFFFu, s, off);
    if (lane == 0) {
        if (is_ci) g_ci[row] = s; else g_cj[row] = s;
    }
}

// ---------------------------------------------------------------------------
// Kernel C (v5): v4 inner loop, d-chunked smem for occupancy.
// q[i,j] = ci[i] + cj[j] + sum_d w'_d |pi[d,i] + pj[d,j]| + b2
// Tile 64i x 32j, 256 threads: ty -> 4 i (2 f32x2 packs), tx -> 2 j.
// CH=64 d-chunks -> 33 KB static smem; __launch_bounds__(256,4):
// 4 blocks/SM x 8 warps = 32 warps/SM, 512 blocks in ONE wave.
// pj staged pre-broadcast-packed {v,v} -> zero pack MOVs in the loop.
// ---------------------------------------------------------------------------
#define CH 64

__global__ void __launch_bounds__(256, 4) pair_kernel(
    const float* __restrict__ b2, float* __restrict__ out)
{
    __shared__ float              pisT[CH][64];   // 16 KB
    __shared__ unsigned long long pjp [CH][32];   // 16 KB
    __shared__ unsigned long long w2p [DD];       //  1 KB

    const int tx  = threadIdx.x;                // 0..15 -> 2 j
    const int ty  = threadIdx.y;                // 0..15 -> 4 i
    const int tid = ty * 16 + tx;
    const int ib  = blockIdx.y * 64;
    const int jb  = blockIdx.x * 32;

    if (tid < DD) {
        const float w = g_W2H[tid];
        w2p[tid] = pack2(w, w);
    }

    const int i0 = ty * 4;                      // local i base (2 packs)
    const int j0 = tx * 2;                      // local j base

    unsigned long long acc[2][2];
    acc[0][0] = acc[0][1] = acc[1][0] = acc[1][1] = 0ULL;

    for (int c = 0; c < 2; c++) {
        const int db = c * CH;
        if (c) __syncthreads();                 // previous chunk consumed

        // stage pi chunk [64 d][64 i]: 1024 float4, coalesced
        #pragma unroll
        for (int it = 0; it < 4; it++) {
            const int idx = tid + it * 256;
            const int d = idx >> 4;
            const int q = idx & 15;
            *(float4*)&pisT[d][q * 4] =
                *(const float4*)&g_PIBT[(db + d) * NN + ib + q * 4];
        }
        // stage pj chunk [64 d][32 j], broadcast-packed {v,v}
        #pragma unroll
        for (int it = 0; it < 8; it++) {
            const int idx = tid + it * 256;
            const int d  = idx >> 5;
            const int js = idx & 31;
            const float v = g_PJT[(db + d) * NN + jb + js];
            pjp[d][js] = pack2(v, v);
        }
        __syncthreads();

        #pragma unroll 8
        for (int dd = 0; dd < CH; dd++) {
            const ulonglong2 aA = *(const ulonglong2*)&pisT[dd][i0];
            const ulonglong2 bB = *(const ulonglong2*)&pjp [dd][j0];
            const unsigned long long wd = w2p[db + dd];

            unsigned long long t;
            t = add2(aA.x, bB.x) & ABS2_MASK;  acc[0][0] = fma2(wd, t, acc[0][0]);
            t = add2(aA.x, bB.y) & ABS2_MASK;  acc[0][1] = fma2(wd, t, acc[0][1]);
            t = add2(aA.y, bB.x) & ABS2_MASK;  acc[1][0] = fma2(wd, t, acc[1][0]);
            t = add2(aA.y, bB.y) & ABS2_MASK;  acc[1][1] = fma2(wd, t, acc[1][1]);
        }
    }

    // Epilogue: 4 rows x 2 cols; add rank-1 terms + b2
    const int ig = ib + i0;
    const int jg = jb + j0;
    const float4 civ = *(const float4*)&g_ci[ig];
    const float2 cjv = *(const float2*)&g_cj[jg];
    const float  bb  = __ldg(b2);
    const float  cia[4] = { civ.x, civ.y, civ.z, civ.w };

    float v[4][2];
    #pragma unroll
    for (int p = 0; p < 2; p++)
        #pragma unroll
        for (int j = 0; j < 2; j++) {
            float lo, hi;
            unpack2(acc[p][j], lo, hi);
            v[2 * p][j]     = lo;
            v[2 * p + 1][j] = hi;
        }

    #pragma unroll
    for (int r = 0; r < 4; r++) {
        const float base = cia[r] + bb;
        float2 o;
        o.x = v[r][0] + cjv.x + base;
        o.y = v[r][1] + cjv.y + base;
        *(float2*)&out[(ig + r) * NN + jg] = o;
    }
}

// ---------------------------------------------------------------------------
// metadata order: z [1024*128], W1 [256*128], b1 [128], W2 [128], b2 [1]
// output: float32 [1024*1024]
// ---------------------------------------------------------------------------
extern "C" void kernel_launch(void* const* d_in, const int* in_sizes, int n_in,
                              void* d_out, int out_size)
{
    const float* z  = (const float*)d_in[0];
    const float* W1 = (const float*)d_in[1];
    const float* b1 = (const float*)d_in[2];
    const float* W2 = (const float*)d_in[3];
    const float* b2 = (const float*)d_in[4];
    float* out = (float*)d_out;

    prep_kernel<<<NN / 8, 1024>>>(z, W1, b1, W2);
    cicj_kernel<<<256, 256>>>();

    dim3 blk(16, 16);
    dim3 grd(NN / 32, NN / 64);
    pair_kernel<<<grd, blk>>>(b2, out);
}

// round 14
// speedup vs baseline: 1.2626x; 1.0010x over previous
#include <cuda_runtime.h>

#define NN 1024
#define DD 128

// ---------------------------------------------------------------------------
// Device scratch (allocation-free)
// ---------------------------------------------------------------------------
__device__ float g_PIB [NN * DD];   // pi + b1, row-major (for ci)
__device__ float g_PIBT[DD * NN];   // pi + b1, transposed [d][i]
__device__ float g_PJ  [NN * DD];   // pj, row-major (for cj)
__device__ float g_PJT [DD * NN];   // pj, transposed [d][j]
__device__ float g_W2H [DD];        // 0.5 * W2
__device__ float g_ci  [NN];
__device__ float g_cj  [NN];

// ---------------------------------------------------------------------------
// f32x2 packed helpers (sm_103a)
// ---------------------------------------------------------------------------
__device__ __forceinline__ unsigned long long pack2(float lo, float hi) {
    unsigned long long r;
    asm("mov.b64 %0, {%1, %2};" : "=l"(r) : "f"(lo), "f"(hi));
    return r;
}
__device__ __forceinline__ void unpack2(unsigned long long v, float& lo, float& hi) {
    asm("mov.b64 {%0, %1}, %2;" : "=f"(lo), "=f"(hi) : "l"(v));
}
__device__ __forceinline__ unsigned long long add2(unsigned long long a, unsigned long long b) {
    unsigned long long r;
    asm("add.rn.f32x2 %0, %1, %2;" : "=l"(r) : "l"(a), "l"(b));
    return r;
}
__device__ __forceinline__ unsigned long long fma2(unsigned long long a, unsigned long long b,
                                                   unsigned long long c) {
    unsigned long long r;
    asm("fma.rn.f32x2 %0, %1, %2, %3;" : "=l"(r) : "l"(a), "l"(b), "l"(c));
    return r;
}
#define ABS2_MASK 0x7FFFFFFF7FFFFFFFULL

// ---------------------------------------------------------------------------
// Kernel A (v7): LSU-minimized GEMM.
// 128 blocks x 512 threads. Thread = (concat col dc = tid&255, half h),
// 4 rows each. z staged TRANSPOSED: zsT[k][row] (pad 12 -> LDS.128 aligned).
// Per k: 1 coalesced scalar LDG (W1 column) + 1 broadcast LDS.128 + 4 FFMA.
// L1tex wavefronts per warp: 256 (was 384 with 2x the LDS) -> LSU ~= FFMA.
// ---------------------------------------------------------------------------
__global__ void __launch_bounds__(512, 1) prep_kernel(
    const float* __restrict__ z, const float* __restrict__ W1,
    const float* __restrict__ b1, const float* __restrict__ W2)
{
    __shared__ float zsT[DD][12];        // [k][row 0..7]; 12-pad: 48B rows, aligned
    const int tid = threadIdx.x;         // 0..511
    const int dc  = tid & 255;           // concat output column
    const int h   = tid >> 8;            // 0/1 -> rows 4h..4h+3
    const int i0  = blockIdx.x * 8;

    if (blockIdx.x == 0 && tid < DD) g_W2H[tid] = 0.5f * W2[tid];

    // Stage z transposed: 1024 elements, coalesced gmem reads
    #pragma unroll
    for (int t = 0; t < 2; t++) {
        const int idx = tid + t * 512;   // 0..1023
        const int r = idx >> 7;          // row 0..7
        const int k = idx & 127;
        zsT[k][r] = z[(i0 + r) * DD + k];
    }
    __syncthreads();

    const bool is_pi = (dc < DD);
    const int  d     = is_pi ? dc : dc - DD;
    const float* wcol = is_pi ? (W1 + d) : (W1 + DD * DD + d);
    const int r0 = 4 * h;

    float a0 = 0.f, a1 = 0.f, a2 = 0.f, a3 = 0.f;

    #pragma unroll 16
    for (int k = 0; k < DD; k++) {
        const float w = __ldg(&wcol[k * DD]);           // coalesced across dc
        const float4 zv = *(const float4*)&zsT[k][r0];  // broadcast LDS.128
        a0 = fmaf(zv.x, w, a0);
        a1 = fmaf(zv.y, w, a1);
        a2 = fmaf(zv.z, w, a2);
        a3 = fmaf(zv.w, w, a3);
    }

    if (is_pi) {
        const float bb = __ldg(&b1[d]);
        a0 += bb; a1 += bb; a2 += bb; a3 += bb;
        g_PIB[(i0 + r0) * DD + d]     = a0;     // coalesced across dc
        g_PIB[(i0 + r0 + 1) * DD + d] = a1;
        g_PIB[(i0 + r0 + 2) * DD + d] = a2;
        g_PIB[(i0 + r0 + 3) * DD + d] = a3;
        *(float4*)&g_PIBT[d * NN + i0 + r0] = make_float4(a0, a1, a2, a3);
    } else {
        g_PJ[(i0 + r0) * DD + d]     = a0;
        g_PJ[(i0 + r0 + 1) * DD + d] = a1;
        g_PJ[(i0 + r0 + 2) * DD + d] = a2;
        g_PJ[(i0 + r0 + 3) * DD + d] = a3;
        *(float4*)&g_PJT[d * NN + i0 + r0] = make_float4(a0, a1, a2, a3);
    }
}

// ---------------------------------------------------------------------------
// Kernel B: ci[i] = g_PIB[i,:] . g_W2H ; cj[j] = g_PJ[j,:] . g_W2H
// ---------------------------------------------------------------------------
__global__ void __launch_bounds__(256) cicj_kernel()
{
    const int warp = blockIdx.x * 8 + (threadIdx.x >> 5);
    const int lane = threadIdx.x & 31;
    const bool is_ci = warp < NN;
    const int  row   = is_ci ? warp : warp - NN;
    const float* src = is_ci ? (g_PIB + row * DD) : (g_PJ + row * DD);

    float4 v = *(const float4*)(src + lane * 4);
    float4 w = *(const float4*)(g_W2H + lane * 4);
    float s = v.x * w.x + v.y * w.y + v.z * w.z + v.w * w.w;
    #pragma unroll
    for (int off = 16; off; off >>= 1)
        s += __shfl_down_sync(0xFFFFFFFFu, s, off);
    if (lane == 0) {
        if (is_ci) g_ci[row] = s; else g_cj[row] = s;
    }
}

// ---------------------------------------------------------------------------
// Kernel C (v5, unchanged): d-chunked single-pass pair kernel.
// q[i,j] = ci[i] + cj[j] + sum_d w'_d |pi[d,i] + pj[d,j]| + b2
// Tile 64i x 32j, 256 threads: ty -> 4 i (2 f32x2 packs), tx -> 2 j.
// CH=64 d-chunks -> 33 KB static smem; 4 blocks/SM, 512 blocks single wave.
// ---------------------------------------------------------------------------
#define CH 64

__global__ void __launch_bounds__(256, 4) pair_kernel(
    const float* __restrict__ b2, float* __restrict__ out)
{
    __shared__ float              pisT[CH][64];   // 16 KB
    __shared__ unsigned long long pjp [CH][32];   // 16 KB
    __shared__ unsigned long long w2p [DD];       //  1 KB

    const int tx  = threadIdx.x;                // 0..15 -> 2 j
    const int ty  = threadIdx.y;                // 0..15 -> 4 i
    const int tid = ty * 16 + tx;
    const int ib  = blockIdx.y * 64;
    const int jb  = blockIdx.x * 32;

    if (tid < DD) {
        const float w = g_W2H[tid];
        w2p[tid] = pack2(w, w);
    }

    const int i0 = ty * 4;                      // local i base (2 packs)
    const int j0 = tx * 2;                      // local j base

    unsigned long long acc[2][2];
    acc[0][0] = acc[0][1] = acc[1][0] = acc[1][1] = 0ULL;

    for (int c = 0; c < 2; c++) {
        const int db = c * CH;
        if (c) __syncthreads();                 // previous chunk consumed

        #pragma unroll
        for (int it = 0; it < 4; it++) {
            const int idx = tid + it * 256;
            const int d = idx >> 4;
            const int q = idx & 15;
            *(float4*)&pisT[d][q * 4] =
                *(const float4*)&g_PIBT[(db + d) * NN + ib + q * 4];
        }
        #pragma unroll
        for (int it = 0; it < 8; it++) {
            const int idx = tid + it * 256;
            const int d  = idx >> 5;
            const int js = idx & 31;
            const float v = g_PJT[(db + d) * NN + jb + js];
            pjp[d][js] = pack2(v, v);
        }
        __syncthreads();

        #pragma unroll 8
        for (int dd = 0; dd < CH; dd++) {
            const ulonglong2 aA = *(const ulonglong2*)&pisT[dd][i0];
            const ulonglong2 bB = *(const ulonglong2*)&pjp [dd][j0];
            const unsigned long long wd = w2p[db + dd];

            unsigned long long t;
            t = add2(aA.x, bB.x) & ABS2_MASK;  acc[0][0] = fma2(wd, t, acc[0][0]);
            t = add2(aA.x, bB.y) & ABS2_MASK;  acc[0][1] = fma2(wd, t, acc[0][1]);
            t = add2(aA.y, bB.x) & ABS2_MASK;  acc[1][0] = fma2(wd, t, acc[1][0]);
            t = add2(aA.y, bB.y) & ABS2_MASK;  acc[1][1] = fma2(wd, t, acc[1][1]);
        }
    }

    // Epilogue: 4 rows x 2 cols; add rank-1 terms + b2
    const int ig = ib + i0;
    const int jg = jb + j0;
    const float4 civ = *(const float4*)&g_ci[ig];
    const float2 cjv = *(const float2*)&g_cj[jg];
    const float  bb  = __ldg(b2);
    const float  cia[4] = { civ.x, civ.y, civ.z, civ.w };

    float v[4][2];
    #pragma unroll
    for (int p = 0; p < 2; p++)
        #pragma unroll
        for (int j = 0; j < 2; j++) {
            float lo, hi;
            unpack2(acc[p][j], lo, hi);
            v[2 * p][j]     = lo;
            v[2 * p + 1][j] = hi;
        }

    #pragma unroll
    for (int r = 0; r < 4; r++) {
        const float base = cia[r] + bb;
        float2 o;
        o.x = v[r][0] + cjv.x + base;
        o.y = v[r][1] + cjv.y + base;
        *(float2*)&out[(ig + r) * NN + jg] = o;
    }
}

// ---------------------------------------------------------------------------
// metadata order: z [1024*128], W1 [256*128], b1 [128], W2 [128], b2 [1]
// output: float32 [1024*1024]
// ---------------------------------------------------------------------------
extern "C" void kernel_launch(void* const* d_in, const int* in_sizes, int n_in,
                              void* d_out, int out_size)
{
    const float* z  = (const float*)d_in[0];
    const float* W1 = (const float*)d_in[1];
    const float* b1 = (const float*)d_in[2];
    const float* W2 = (const float*)d_in[3];
    const float* b2 = (const float*)d_in[4];
    float* out = (float*)d_out;

    prep_kernel<<<NN / 8, 512>>>(z, W1, b1, W2);
    cicj_kernel<<<256, 256>>>();

    dim3 blk(16, 16);
    dim3 grd(NN / 32, NN / 64);
    pair_kernel<<<grd, blk>>>(b2, out);
}

// round 16
// speedup vs baseline: 1.3498x; 1.0691x over previous
#include <cuda_runtime.h>

#define NN 1024
#define DD 128
#define DH 64    // d-range per z-slice of pair_kernel

// ---------------------------------------------------------------------------
// Device scratch (allocation-free)
// ---------------------------------------------------------------------------
__device__ float g_PIB [NN * DD];   // pi + b1, row-major (for ci)
__device__ float g_PIBT[DD * NN];   // pi + b1, transposed [d][i]
__device__ float g_PJ  [NN * DD];   // pj, row-major (for cj)
__device__ float g_PJT [DD * NN];   // pj, transposed [d][j]
__device__ float g_W2H [DD];        // 0.5 * W2
__device__ float g_ci  [NN];
__device__ float g_cj  [NN];
__device__ float g_P1  [NN * NN];   // partial sums for d in [64,128)

// ---------------------------------------------------------------------------
// f32x2 packed helpers (sm_103a)
// ---------------------------------------------------------------------------
__device__ __forceinline__ unsigned long long pack2(float lo, float hi) {
    unsigned long long r;
    asm("mov.b64 %0, {%1, %2};" : "=l"(r) : "f"(lo), "f"(hi));
    return r;
}
__device__ __forceinline__ void unpack2(unsigned long long v, float& lo, float& hi) {
    asm("mov.b64 {%0, %1}, %2;" : "=f"(lo), "=f"(hi) : "l"(v));
}
__device__ __forceinline__ unsigned long long add2(unsigned long long a, unsigned long long b) {
    unsigned long long r;
    asm("add.rn.f32x2 %0, %1, %2;" : "=l"(r) : "l"(a), "l"(b));
    return r;
}
__device__ __forceinline__ unsigned long long fma2(unsigned long long a, unsigned long long b,
                                                   unsigned long long c) {
    unsigned long long r;
    asm("fma.rn.f32x2 %0, %1, %2, %3;" : "=l"(r) : "l"(a), "l"(b), "l"(c));
    return r;
}
#define ABS2_MASK 0x7FFFFFFF7FFFFFFFULL

// ---------------------------------------------------------------------------
// Kernel A (v7, proven in r13/r14): LSU-minimized GEMM.
// 128 blocks x 512 threads. Thread = (concat col dc = tid&255, half h),
// 4 rows each. z staged transposed: zsT[k][row] (pad 12, LDS.128-aligned).
// Per k: 1 coalesced scalar LDG (W1 column) + 1 broadcast LDS.128 + 4 FFMA.
// ---------------------------------------------------------------------------
__global__ void __launch_bounds__(512, 1) prep_kernel(
    const float* __restrict__ z, const float* __restrict__ W1,
    const float* __restrict__ b1, const float* __restrict__ W2)
{
    __shared__ float zsT[DD][12];        // [k][row 0..7]
    const int tid = threadIdx.x;         // 0..511
    const int dc  = tid & 255;           // concat output column
    const int h   = tid >> 8;            // 0/1 -> rows 4h..4h+3
    const int i0  = blockIdx.x * 8;

    if (blockIdx.x == 0 && tid < DD) g_W2H[tid] = 0.5f * W2[tid];

    #pragma unroll
    for (int t = 0; t < 2; t++) {
        const int idx = tid + t * 512;   // 0..1023
        const int r = idx >> 7;          // row 0..7
        const int k = idx & 127;
        zsT[k][r] = z[(i0 + r) * DD + k];
    }
    __syncthreads();

    const bool is_pi = (dc < DD);
    const int  d     = is_pi ? dc : dc - DD;
    const float* wcol = is_pi ? (W1 + d) : (W1 + DD * DD + d);
    const int r0 = 4 * h;

    float a0 = 0.f, a1 = 0.f, a2 = 0.f, a3 = 0.f;

    #pragma unroll 16
    for (int k = 0; k < DD; k++) {
        const float w = __ldg(&wcol[k * DD]);           // coalesced across dc
        const float4 zv = *(const float4*)&zsT[k][r0];  // broadcast LDS.128
        a0 = fmaf(zv.x, w, a0);
        a1 = fmaf(zv.y, w, a1);
        a2 = fmaf(zv.z, w, a2);
        a3 = fmaf(zv.w, w, a3);
    }

    if (is_pi) {
        const float bb = __ldg(&b1[d]);
        a0 += bb; a1 += bb; a2 += bb; a3 += bb;
        g_PIB[(i0 + r0) * DD + d]     = a0;
        g_PIB[(i0 + r0 + 1) * DD + d] = a1;
        g_PIB[(i0 + r0 + 2) * DD + d] = a2;
        g_PIB[(i0 + r0 + 3) * DD + d] = a3;
        *(float4*)&g_PIBT[d * NN + i0 + r0] = make_float4(a0, a1, a2, a3);
    } else {
        g_PJ[(i0 + r0) * DD + d]     = a0;
        g_PJ[(i0 + r0 + 1) * DD + d] = a1;
        g_PJ[(i0 + r0 + 2) * DD + d] = a2;
        g_PJ[(i0 + r0 + 3) * DD + d] = a3;
        *(float4*)&g_PJT[d * NN + i0 + r0] = make_float4(a0, a1, a2, a3);
    }
}

// ---------------------------------------------------------------------------
// Kernel B: ci[i] = g_PIB[i,:] . g_W2H ; cj[j] = g_PJ[j,:] . g_W2H
// ---------------------------------------------------------------------------
__global__ void __launch_bounds__(256) cicj_kernel()
{
    const int warp = blockIdx.x * 8 + (threadIdx.x >> 5);
    const int lane = threadIdx.x & 31;
    const bool is_ci = warp < NN;
    const int  row   = is_ci ? warp : warp - NN;
    const float* src = is_ci ? (g_PIB + row * DD) : (g_PJ + row * DD);

    float4 v = *(const float4*)(src + lane * 4);
    float4 w = *(const float4*)(g_W2H + lane * 4);
    float s = v.x * w.x + v.y * w.y + v.z * w.z + v.w * w.w;
    #pragma unroll
    for (int off = 16; off; off >>= 1)
        s += __shfl_down_sync(0xFFFFFFFFu, s, off);
    if (lane == 0) {
        if (is_ci) g_ci[row] = s; else g_cj[row] = s;
    }
}

// ---------------------------------------------------------------------------
// Kernel C (r9-proven d-split): partial[i,j] over d-range of 64.
// Grid (16,16,2): z selects d in [z*64,(z+1)*64) and target (out / g_P1).
// 64i x 64j tile, 256 threads (16x16), 4i x 4j per thread, f32x2 packed.
// 512 blocks total -> ~28 warps/SM resident.
// ---------------------------------------------------------------------------
#define TPAD 68   // row stride in floats (64 + 4), keeps 16B alignment

__global__ void __launch_bounds__(256, 4) pair_kernel(float* __restrict__ out)
{
    __shared__ float pisT[DH][TPAD];            // ~17.4 KB
    __shared__ float pjs [DH][TPAD];            // ~17.4 KB
    __shared__ unsigned long long w2p[DH];      //  512 B

    const int tx  = threadIdx.x;                // 0..15 -> 4 j
    const int ty  = threadIdx.y;                // 0..15 -> 4 i
    const int tid = ty * 16 + tx;
    const int ib  = blockIdx.y * 64;
    const int jb  = blockIdx.x * 64;
    const int db  = blockIdx.z * DH;            // d-range base

    for (int idx = tid; idx < DH * 16; idx += 256) {
        const int d = idx >> 4;
        const int q = idx & 15;
        *(float4*)&pisT[d][q * 4] =
            *(const float4*)&g_PIBT[(db + d) * NN + ib + q * 4];
        *(float4*)&pjs[d][q * 4] =
            *(const float4*)&g_PJT [(db + d) * NN + jb + q * 4];
    }
    if (tid < DH) {
        const float w = g_W2H[db + tid];
        w2p[tid] = pack2(w, w);
    }
    __syncthreads();

    const int i0 = ty * 4;                      // local i base
    const int j0 = tx * 4;                      // local j base

    unsigned long long acc[2][4];               // [i-pair][j]
    #pragma unroll
    for (int p = 0; p < 2; p++)
        #pragma unroll
        for (int j = 0; j < 4; j++) acc[p][j] = 0ULL;

    #pragma unroll 4
    for (int d = 0; d < DH; d++) {
        const ulonglong2 aA = *(const ulonglong2*)&pisT[d][i0];
        const float4 bf = *(const float4*)&pjs[d][j0];
        const unsigned long long bp[4] = {
            pack2(bf.x, bf.x), pack2(bf.y, bf.y),
            pack2(bf.z, bf.z), pack2(bf.w, bf.w) };
        const unsigned long long wd = w2p[d];

        #pragma unroll
        for (int j = 0; j < 4; j++) {
            unsigned long long t0 = add2(aA.x, bp[j]) & ABS2_MASK;
            acc[0][j] = fma2(wd, t0, acc[0][j]);
            unsigned long long t1 = add2(aA.y, bp[j]) & ABS2_MASK;
            acc[1][j] = fma2(wd, t1, acc[1][j]);
        }
    }

    // Write raw partials (rank-1 terms + b2 added in combine)
    float* dst = (blockIdx.z == 0) ? out : g_P1;

    float v[4][4];
    #pragma unroll
    for (int p = 0; p < 2; p++)
        #pragma unroll
        for (int j = 0; j < 4; j++) {
            float lo, hi;
            unpack2(acc[p][j], lo, hi);
            v[2 * p][j]     = lo;
            v[2 * p + 1][j] = hi;
        }

    #pragma unroll
    for (int r = 0; r < 4; r++) {
        float4 o;
        o.x = v[r][0]; o.y = v[r][1]; o.z = v[r][2]; o.w = v[r][3];
        *(float4*)&dst[(ib + i0 + r) * NN + jb + j0] = o;
    }
}

// ---------------------------------------------------------------------------
// Kernel D (v2): out = out + g_P1 + ci[i] + cj[j] + b2.
// 512 blocks x 256 threads, 8 floats (2 float4) per thread ->
// 4 independent LDG.128 in flight per thread (MLP 4+), BW-bound ~2.5us.
// ---------------------------------------------------------------------------
__global__ void __launch_bounds__(256) combine_kernel(
    const float* __restrict__ b2, float* __restrict__ out)
{
    const int idx = (blockIdx.x * 256 + threadIdx.x) * 8;
    const int i = idx >> 10;
    const int j = idx & (NN - 1);

    float4 a0 = *(float4*)&out[idx];
    float4 a1 = *(float4*)&out[idx + 4];
    const float4 p0 = *(const float4*)&g_P1[idx];
    const float4 p1 = *(const float4*)&g_P1[idx + 4];
    const float4 c0 = *(const float4*)&g_cj[j];
    const float4 c1 = *(const float4*)&g_cj[j + 4];
    const float base = g_ci[i] + __ldg(b2);

    a0.x += p0.x + c0.x + base;
    a0.y += p0.y + c0.y + base;
    a0.z += p0.z + c0.z + base;
    a0.w += p0.w + c0.w + base;
    a1.x += p1.x + c1.x + base;
    a1.y += p1.y + c1.y + base;
    a1.z += p1.z + c1.z + base;
    a1.w += p1.w + c1.w + base;

    *(float4*)&out[idx]     = a0;
    *(float4*)&out[idx + 4] = a1;
}

// ---------------------------------------------------------------------------
// metadata order: z [1024*128], W1 [256*128], b1 [128], W2 [128], b2 [1]
// output: float32 [1024*1024]
// ---------------------------------------------------------------------------
extern "C" void kernel_launch(void* const* d_in, const int* in_sizes, int n_in,
                              void* d_out, int out_size)
{
    const float* z  = (const float*)d_in[0];
    const float* W1 = (const float*)d_in[1];
    const float* b1 = (const float*)d_in[2];
    const float* W2 = (const float*)d_in[3];
    const float* b2 = (const float*)d_in[4];
    float* out = (float*)d_out;

    prep_kernel<<<NN / 8, 512>>>(z, W1, b1, W2);
    cicj_kernel<<<256, 256>>>();

    dim3 blk(16, 16);
    dim3 grd(NN / 64, NN / 64, 2);
    pair_kernel<<<grd, blk>>>(out);

    combine_kernel<<<NN * NN / (256 * 8), 256>>>(b2, out);
}